// round 3
// baseline (speedup 1.0000x reference)
#include <cuda_runtime.h>
#include <math.h>

#define D_RES  1024
#define NH     16
#define DH     64
#define DMLP   4096
#define SEQ    2048
#define BATCH  2
#define NTOK   (BATCH*SEQ)      /* 4096 */
#define N3     (3*D_RES)        /* 3072 */
#define EPSLN  1e-5f
#define IGNORE_VAL (-100000.0f)

/* ------------------------------------------------------------------ */
/* Scratch: __device__ globals (no allocation allowed)                 */
/* ------------------------------------------------------------------ */
__device__ float g_Bqkv[D_RES * N3];                 /* 12 MB packed [d][3072]  */
__device__ float g_bias_qkv[N3];
__device__ float g_xln[(size_t)NTOK * D_RES];        /* 16 MB */
__device__ float g_qkv[(size_t)NTOK * N3];           /* 48 MB */
__device__ float g_scores[(size_t)BATCH * NH * SEQ * SEQ]; /* 512 MB */
__device__ float g_z[(size_t)NTOK * D_RES];          /* 16 MB */
__device__ float g_resid_mid[(size_t)NTOK * D_RES];  /* 16 MB */
__device__ float g_y[(size_t)NTOK * D_RES];          /* 16 MB */
__device__ float g_post[(size_t)NTOK * DMLP];        /* 64 MB */

/* ------------------------------------------------------------------ */
/* Pack QKV weights into one [1024 x 3072] row-major B matrix + bias   */
/* ------------------------------------------------------------------ */
__global__ void pack_qkv_k(const float* __restrict__ WQ, const float* __restrict__ WK,
                           const float* __restrict__ WV, const float* __restrict__ bQ,
                           const float* __restrict__ bK, const float* __restrict__ bV) {
    int idx = blockIdx.x * blockDim.x + threadIdx.x;
    if (idx < D_RES * N3) {
        int d = idx / N3;
        int n = idx % N3;
        int sel = n / D_RES;              /* 0=Q 1=K 2=V */
        int c   = n % D_RES;              /* h*64+e */
        int h = c / DH, e = c % DH;
        const float* W = (sel == 0) ? WQ : (sel == 1) ? WK : WV;
        g_Bqkv[idx] = W[((size_t)h * D_RES + d) * DH + e];
    }
    if (idx < N3) {
        const float* bb = (idx < D_RES) ? bQ : (idx < 2 * D_RES) ? bK : bV;
        g_bias_qkv[idx] = bb[idx % D_RES];
    }
}

/* ------------------------------------------------------------------ */
/* LayerNorm: one block per token row                                  */
/* ------------------------------------------------------------------ */
__global__ void layernorm_k(const float* __restrict__ in, const float* __restrict__ w,
                            const float* __restrict__ b, float* __restrict__ out) {
    int row = blockIdx.x;
    const float* x = in + (size_t)row * D_RES;
    float* o = out + (size_t)row * D_RES;
    __shared__ float red[256];
    int t = threadIdx.x;

    float s = 0.f;
    for (int i = t; i < D_RES; i += 256) s += x[i];
    red[t] = s; __syncthreads();
    for (int k = 128; k > 0; k >>= 1) { if (t < k) red[t] += red[t + k]; __syncthreads(); }
    float mean = red[0] * (1.f / D_RES);
    __syncthreads();

    float v = 0.f;
    for (int i = t; i < D_RES; i += 256) { float c = x[i] - mean; v += c * c; }
    red[t] = v; __syncthreads();
    for (int k = 128; k > 0; k >>= 1) { if (t < k) red[t] += red[t + k]; __syncthreads(); }
    float inv = rsqrtf(red[0] * (1.f / D_RES) + EPSLN);

    for (int i = t; i < D_RES; i += 256)
        o[i] = (x[i] - mean) * inv * w[i] + b[i];
}

/* ------------------------------------------------------------------ */
/* Generic tiled SGEMM core: C_tile = A[M,K] * B[K,N], 8x8 microtiles  */
/* ------------------------------------------------------------------ */
template <int BM, int BN, int BK>
struct GemmCore {
    static const int TX = BN / 8;
    static const int TY = BM / 8;
    static const int NT = TX * TY;
    static const int PA = BM + 4;
    static const int PB = BN + 4;

    /* A,B already offset to this block's row/col. kEnd multiple of BK. */
    __device__ static void run(const float* __restrict__ A, int lda,
                               const float* __restrict__ B, int ldb,
                               int kEnd, float (&acc)[8][8]) {
        __shared__ float As[BK][PA];   /* transposed: As[k][m] */
        __shared__ float Bs[BK][PB];   /* Bs[k][n] */
        int t  = threadIdx.x;
        int tx = t % TX, ty = t / TX;

        for (int k0 = 0; k0 < kEnd; k0 += BK) {
            /* load A tile (BM x BK), float4 along K, transpose into smem */
            #pragma unroll
            for (int i = 0; i < (BM * BK / 4) / NT; i++) {
                int idx = t + i * NT;
                int r  = idx / (BK / 4);
                int c4 = (idx % (BK / 4)) * 4;
                float4 v = *(const float4*)(A + (size_t)r * lda + k0 + c4);
                As[c4 + 0][r] = v.x; As[c4 + 1][r] = v.y;
                As[c4 + 2][r] = v.z; As[c4 + 3][r] = v.w;
            }
            /* load B tile (BK x BN), float4 along N */
            #pragma unroll
            for (int i = 0; i < (BK * BN / 4) / NT; i++) {
                int idx = t + i * NT;
                int r  = idx / (BN / 4);
                int c4 = (idx % (BN / 4)) * 4;
                *(float4*)(&Bs[r][c4]) = *(const float4*)(B + (size_t)(k0 + r) * ldb + c4);
            }
            __syncthreads();
            #pragma unroll
            for (int kk = 0; kk < BK; kk++) {
                float a[8], b[8];
                *(float4*)(a)     = *(float4*)(&As[kk][ty * 8]);
                *(float4*)(a + 4) = *(float4*)(&As[kk][ty * 8 + 4]);
                *(float4*)(b)     = *(float4*)(&Bs[kk][tx * 8]);
                *(float4*)(b + 4) = *(float4*)(&Bs[kk][tx * 8 + 4]);
                #pragma unroll
                for (int i = 0; i < 8; i++)
                    #pragma unroll
                    for (int j = 0; j < 8; j++)
                        acc[i][j] += a[i] * b[j];
            }
            __syncthreads();
        }
    }
};

__device__ __forceinline__ float gelu_exact(float x) {
    return 0.5f * x * (1.f + erff(x * 0.70710678118654752f));
}

enum { EPI_NONE = 0, EPI_BIAS = 1, EPI_BIAS_RES = 2, EPI_BIAS_GELU = 3 };

template <int BM, int BN, int BK, int EPI>
__global__ void sgemm_k(const float* __restrict__ A, int lda,
                        const float* __restrict__ B, int ldb,
                        float* __restrict__ C, int ldc, int K,
                        const float* __restrict__ bias,
                        const float* __restrict__ res, int ldres) {
    const int TX = BN / 8, TY = BM / 8;
    int bm = blockIdx.y * BM;
    int bn = blockIdx.x * BN;
    float acc[8][8] = {};
    GemmCore<BM, BN, BK>::run(A + (size_t)bm * lda, lda, B + bn, ldb, K, acc);

    int t = threadIdx.x;
    int tx = t % TX, ty = t / TX;
    #pragma unroll
    for (int i = 0; i < 8; i++) {
        int row = bm + ty * 8 + i;
        #pragma unroll
        for (int j = 0; j < 8; j++) {
            int col = bn + tx * 8 + j;
            float v = acc[i][j];
            if (EPI >= EPI_BIAS) v += bias[col];
            if (EPI == EPI_BIAS_RES)  v += res[(size_t)row * ldres + col];
            if (EPI == EPI_BIAS_GELU) v = gelu_exact(v);
            C[(size_t)row * ldc + col] = v;
        }
    }
}

/* ------------------------------------------------------------------ */
/* Attention scores: S = Q K^T / 8 with causal mask (64x64 tiles)      */
/* ------------------------------------------------------------------ */
__global__ void scores_k(const float* __restrict__ qkv, float* __restrict__ scores) {
    int kt = blockIdx.x, qt = blockIdx.y, bh = blockIdx.z;
    if (kt > qt) return;
    int b = bh / NH, h = bh % NH;

    __shared__ float Qs[DH][68];  /* [e][qrow] */
    __shared__ float Ks[DH][68];  /* [e][krow] */
    const float* qbase = qkv + (size_t)b * SEQ * N3 + h * DH;
    const float* kbase = qbase + D_RES;

    int t = threadIdx.x;
    int r0 = t >> 4;
    int e4 = (t & 15) * 4;
    #pragma unroll
    for (int i = 0; i < 4; i++) {
        int r = r0 + i * 16;
        float4 q4 = *(const float4*)(qbase + (size_t)(qt * 64 + r) * N3 + e4);
        Qs[e4 + 0][r] = q4.x; Qs[e4 + 1][r] = q4.y;
        Qs[e4 + 2][r] = q4.z; Qs[e4 + 3][r] = q4.w;
        float4 k4 = *(const float4*)(kbase + (size_t)(kt * 64 + r) * N3 + e4);
        Ks[e4 + 0][r] = k4.x; Ks[e4 + 1][r] = k4.y;
        Ks[e4 + 2][r] = k4.z; Ks[e4 + 3][r] = k4.w;
    }
    __syncthreads();

    float acc[4][4] = {};
    int tx = t & 15, ty = t >> 4;
    #pragma unroll
    for (int e = 0; e < DH; e++) {
        float4 a4 = *(float4*)(&Qs[e][ty * 4]);
        float4 b4 = *(float4*)(&Ks[e][tx * 4]);
        float a[4] = {a4.x, a4.y, a4.z, a4.w};
        float bb[4] = {b4.x, b4.y, b4.z, b4.w};
        #pragma unroll
        for (int i = 0; i < 4; i++)
            #pragma unroll
            for (int j = 0; j < 4; j++)
                acc[i][j] += a[i] * bb[j];
    }

    float* out = scores + (size_t)bh * SEQ * SEQ;
    #pragma unroll
    for (int i = 0; i < 4; i++) {
        int qg = qt * 64 + ty * 4 + i;
        #pragma unroll
        for (int j = 0; j < 4; j++) {
            int kg = kt * 64 + tx * 4 + j;
            out[(size_t)qg * SEQ + kg] = (kg <= qg) ? acc[i][j] * 0.125f : IGNORE_VAL;
        }
    }
}

/* ------------------------------------------------------------------ */
/* Row softmax (causal): one block per row, row cached in smem.        */
/* Zero-fills up to the 128-aligned boundary read by the PV GEMM.      */
/* ------------------------------------------------------------------ */
__global__ void softmax_k(float* __restrict__ scores) {
    int s  = blockIdx.x;
    int bh = blockIdx.y;
    float* row = scores + (size_t)bh * SEQ * SEQ + (size_t)s * SEQ;
    int n = s + 1;

    __shared__ float srow[SEQ];
    __shared__ float red[256];
    int t = threadIdx.x;

    float mx = -3.0e38f;
    for (int i = t; i < n; i += 256) { float v = row[i]; srow[i] = v; mx = fmaxf(mx, v); }
    red[t] = mx; __syncthreads();
    for (int k = 128; k > 0; k >>= 1) { if (t < k) red[t] = fmaxf(red[t], red[t + k]); __syncthreads(); }
    mx = red[0]; __syncthreads();

    float ss = 0.f;
    for (int i = t; i < n; i += 256) { float e = expf(srow[i] - mx); srow[i] = e; ss += e; }
    red[t] = ss; __syncthreads();
    for (int k = 128; k > 0; k >>= 1) { if (t < k) red[t] += red[t + k]; __syncthreads(); }
    float inv = 1.f / red[0];

    for (int i = t; i < n; i += 256) row[i] = srow[i] * inv;
    int lim = ((s >> 7) + 1) << 7;           /* PV k-loop reads up to tile end */
    for (int i = n + t; i < lim; i += 256) row[i] = 0.f;
}

/* ------------------------------------------------------------------ */
/* Z = P * V  (batched over b,h; causal k-limit). BM=128, BN=64.       */
/* ------------------------------------------------------------------ */
template <int BM, int BN, int BK>
__global__ void pv_gemm_k(const float* __restrict__ scores,
                          const float* __restrict__ qkv,
                          float* __restrict__ Z) {
    int bh = blockIdx.z;
    int b = bh / NH, h = bh % NH;
    int bm = blockIdx.y * BM;

    const float* A = scores + (size_t)bh * SEQ * SEQ + (size_t)bm * SEQ;
    const float* B = qkv + (size_t)b * SEQ * N3 + 2 * D_RES + h * DH;  /* V */

    float acc[8][8] = {};
    int kEnd = bm + BM;   /* causal: P[row][k]==0 for k>row; rows<bm+BM */
    GemmCore<BM, BN, BK>::run(A, SEQ, B, N3, kEnd, acc);

    const int TX = BN / 8;
    int t = threadIdx.x;
    int tx = t % TX, ty = t / TX;
    float* C = Z + (size_t)b * SEQ * D_RES + h * DH;
    #pragma unroll
    for (int i = 0; i < 8; i++) {
        int row = bm + ty * 8 + i;
        #pragma unroll
        for (int j = 0; j < 8; j++) {
            int col = tx * 8 + j;
            C[(size_t)row * D_RES + col] = acc[i][j];
        }
    }
}

/* ------------------------------------------------------------------ */
/* Launch                                                              */
/* ------------------------------------------------------------------ */
extern "C" void kernel_launch(void* const* d_in, const int* in_sizes, int n_in,
                              void* d_out, int out_size) {
    const float* resid_pre = (const float*)d_in[0];
    const float* ln1_w = (const float*)d_in[1];
    const float* ln1_b = (const float*)d_in[2];
    const float* WQ = (const float*)d_in[3];
    const float* bQ = (const float*)d_in[4];
    const float* WK = (const float*)d_in[5];
    const float* bK = (const float*)d_in[6];
    const float* WV = (const float*)d_in[7];
    const float* bV = (const float*)d_in[8];
    const float* WO = (const float*)d_in[9];    /* [16,64,1024] == [1024,1024] row-major */
    const float* bO = (const float*)d_in[10];
    const float* ln2_w = (const float*)d_in[11];
    const float* ln2_b = (const float*)d_in[12];
    const float* Win  = (const float*)d_in[13]; /* [1024,4096] */
    const float* bin  = (const float*)d_in[14];
    const float* Wout = (const float*)d_in[15]; /* [4096,1024] */
    const float* bout = (const float*)d_in[16];
    float* out = (float*)d_out;

    float *p_Bqkv, *p_bias, *p_xln, *p_qkv, *p_scores, *p_z, *p_mid, *p_y, *p_post;
    cudaGetSymbolAddress((void**)&p_Bqkv, g_Bqkv);
    cudaGetSymbolAddress((void**)&p_bias, g_bias_qkv);
    cudaGetSymbolAddress((void**)&p_xln, g_xln);
    cudaGetSymbolAddress((void**)&p_qkv, g_qkv);
    cudaGetSymbolAddress((void**)&p_scores, g_scores);
    cudaGetSymbolAddress((void**)&p_z, g_z);
    cudaGetSymbolAddress((void**)&p_mid, g_resid_mid);
    cudaGetSymbolAddress((void**)&p_y, g_y);
    cudaGetSymbolAddress((void**)&p_post, g_post);

    /* 1. pack QKV weights + bias */
    pack_qkv_k<<<(D_RES * N3 + 255) / 256, 256>>>(WQ, WK, WV, bQ, bK, bV);

    /* 2. LN1 */
    layernorm_k<<<NTOK, 256>>>(resid_pre, ln1_w, ln1_b, p_xln);

    /* 3. QKV = xln @ Bqkv + bias   [4096,1024]x[1024,3072] */
    sgemm_k<128, 128, 16, EPI_BIAS><<<dim3(N3 / 128, NTOK / 128), 256>>>(
        p_xln, D_RES, p_Bqkv, N3, p_qkv, N3, D_RES, p_bias, nullptr, 0);

    /* 4. scores = Q K^T / 8 + causal mask */
    scores_k<<<dim3(SEQ / 64, SEQ / 64, BATCH * NH), 256>>>(p_qkv, p_scores);

    /* 5. softmax per row */
    softmax_k<<<dim3(SEQ, BATCH * NH), 256>>>(p_scores);

    /* 6. Z = P V   (batched, causal-limited K) */
    pv_gemm_k<128, 64, 16><<<dim3(1, SEQ / 128, BATCH * NH), 128>>>(p_scores, p_qkv, p_z);

    /* 7. resid_mid = Z @ W_O + b_O + resid_pre */
    sgemm_k<128, 128, 16, EPI_BIAS_RES><<<dim3(D_RES / 128, NTOK / 128), 256>>>(
        p_z, D_RES, WO, D_RES, p_mid, D_RES, D_RES, bO, resid_pre, D_RES);

    /* 8. LN2 */
    layernorm_k<<<NTOK, 256>>>(p_mid, ln2_w, ln2_b, p_y);

    /* 9. post = gelu(y @ W_in + b_in)   [4096,1024]x[1024,4096] */
    sgemm_k<128, 128, 16, EPI_BIAS_GELU><<<dim3(DMLP / 128, NTOK / 128), 256>>>(
        p_y, D_RES, Win, DMLP, p_post, DMLP, D_RES, bin, nullptr, 0);

    /* 10. out = post @ W_out + b_out + resid_mid */
    sgemm_k<128, 128, 16, EPI_BIAS_RES><<<dim3(D_RES / 128, NTOK / 128), 256>>>(
        p_post, DMLP, Wout, D_RES, out, D_RES, DMLP, bout, p_mid, D_RES);
}

// round 6
// speedup vs baseline: 2.6771x; 2.6771x over previous
#include <cuda_runtime.h>
#include <math.h>
#include <stdint.h>

#define D_RES  1024
#define NH     16
#define DH     64
#define DMLP   4096
#define SEQ    2048
#define BATCH  2
#define NTOK   (BATCH*SEQ)      /* 4096 */
#define N3     (3*D_RES)        /* 3072 */
#define EPSLN  1e-5f
#define IGNORE_VAL (-100000.0f)

/* ------------------------------------------------------------------ */
/* Scratch: __device__ globals                                         */
/* ------------------------------------------------------------------ */
__device__ float g_Wqkv_t[N3 * D_RES];               /* 12 MB  [3072][1024] */
__device__ float g_bias_qkv[N3];
__device__ float g_WOt[D_RES * D_RES];               /*  4 MB */
__device__ float g_Wint[DMLP * D_RES];               /* 16 MB */
__device__ float g_Woutt[D_RES * DMLP];              /* 16 MB */
__device__ float g_xln[(size_t)NTOK * D_RES];        /* 16 MB */
__device__ float g_qkv[(size_t)NTOK * N3];           /* 48 MB */
__device__ float g_vt[(size_t)BATCH * NH * DH * SEQ];/* 16 MB  [bh][e][k] */
__device__ float g_scores[(size_t)BATCH * NH * SEQ * SEQ]; /* 512 MB */
__device__ float g_z[(size_t)NTOK * D_RES];          /* 16 MB */
__device__ float g_resid_mid[(size_t)NTOK * D_RES];  /* 16 MB */
__device__ float g_y[(size_t)NTOK * D_RES];          /* 16 MB */
__device__ float g_post[(size_t)NTOK * DMLP];        /* 64 MB */

/* ------------------------------------------------------------------ */
/* PTX helpers (sm_103 base ISA: cp.async + ldmatrix + mma.sync tf32)  */
/* ------------------------------------------------------------------ */
__device__ __forceinline__ uint32_t smem_u32(const void* p) {
    uint32_t a;
    asm("{ .reg .u64 t; cvta.to.shared.u64 t, %1; cvt.u32.u64 %0, t; }" : "=r"(a) : "l"(p));
    return a;
}
__device__ __forceinline__ void cp16(uint32_t dst, const float* src) {
    asm volatile("cp.async.ca.shared.global [%0], [%1], 16;" :: "r"(dst), "l"(src));
}
#define CP_COMMIT()  asm volatile("cp.async.commit_group;" ::: "memory")
#define CP_WAIT0()   asm volatile("cp.async.wait_group 0;" ::: "memory")
#define CP_WAIT1()   asm volatile("cp.async.wait_group 1;" ::: "memory")

__device__ __forceinline__ void ldsm4(uint32_t a, uint32_t& r0, uint32_t& r1,
                                      uint32_t& r2, uint32_t& r3) {
    asm volatile("ldmatrix.sync.aligned.m8n8.x4.shared.b16 {%0,%1,%2,%3}, [%4];"
                 : "=r"(r0), "=r"(r1), "=r"(r2), "=r"(r3) : "r"(a));
}
__device__ __forceinline__ void cvt_tf32(uint32_t& x) {
    asm("cvt.rna.tf32.f32 %0, %0;" : "+r"(x));
}
__device__ __forceinline__ void mma_tf32(float* c, const uint32_t* a,
                                         uint32_t b0, uint32_t b1) {
    asm volatile("mma.sync.aligned.m16n8k8.row.col.f32.tf32.tf32.f32 "
                 "{%0,%1,%2,%3}, {%4,%5,%6,%7}, {%8,%9}, {%0,%1,%2,%3};"
                 : "+f"(c[0]), "+f"(c[1]), "+f"(c[2]), "+f"(c[3])
                 : "r"(a[0]), "r"(a[1]), "r"(a[2]), "r"(a[3]), "r"(b0), "r"(b1));
}

/* ------------------------------------------------------------------ */
/* Warp-MMA core. CTA tile BM x BN, K-chunk 32, warp tile 64x32.       */
/* SMEM rows: 36 floats (144 B) -> ldmatrix conflict-free.             */
/* ------------------------------------------------------------------ */
#define STR 36

template <int ROWS, int NT>
__device__ __forceinline__ void stage_tile(uint32_t s, const float* __restrict__ g,
                                           int ld, int k0) {
    #pragma unroll
    for (int i = 0; i < (ROWS * 8) / NT; i++) {
        int u = threadIdx.x + i * NT;
        int r = u >> 3, c = u & 7;
        cp16(s + (uint32_t)(r * STR + c * 4) * 4, g + (size_t)r * ld + k0 + c * 4);
    }
}

template <int BM, int BN>
__device__ __forceinline__ void compute_chunk(uint32_t a_s, uint32_t b_s,
                                              float (&acc)[4][4][4]) {
    const int WN = BN / 32;
    int lane = threadIdx.x & 31, wid = threadIdx.x >> 5;
    int wm = wid / WN, wn = wid % WN;
    uint32_t ab = a_s + (uint32_t)(((wm * 64 + (lane & 15)) * STR + ((lane >> 4) << 2)) * 4);
    uint32_t bb = b_s + (uint32_t)(((wn * 32 + (lane & 7) + ((lane >> 4) << 3)) * STR
                                    + (((lane >> 3) & 1) << 2)) * 4);
    #pragma unroll
    for (int ks = 0; ks < 4; ks++) {
        uint32_t af[4][4], bf[4][2];
        #pragma unroll
        for (int mt = 0; mt < 4; mt++)
            ldsm4(ab + mt * (16 * STR * 4) + ks * 32,
                  af[mt][0], af[mt][1], af[mt][2], af[mt][3]);
        #pragma unroll
        for (int p = 0; p < 2; p++)
            ldsm4(bb + p * (16 * STR * 4) + ks * 32,
                  bf[2 * p][0], bf[2 * p][1], bf[2 * p + 1][0], bf[2 * p + 1][1]);
        #pragma unroll
        for (int mt = 0; mt < 4; mt++)
            #pragma unroll
            for (int j = 0; j < 4; j++) cvt_tf32(af[mt][j]);
        #pragma unroll
        for (int nt = 0; nt < 4; nt++) { cvt_tf32(bf[nt][0]); cvt_tf32(bf[nt][1]); }
        #pragma unroll
        for (int mt = 0; mt < 4; mt++)
            #pragma unroll
            for (int nt = 0; nt < 4; nt++)
                mma_tf32(acc[mt][nt], af[mt], bf[nt][0], bf[nt][1]);
    }
}

/* A[M,K] row-major (lda), Bt[N,K] row-major (ldb). nc K-chunks of 32. */
template <int BM, int BN>
__device__ __forceinline__ void mma_run(float* sm,
        const float* __restrict__ A, int lda,
        const float* __restrict__ Bt, int ldb, int nc, float (&acc)[4][4][4]) {
    const int NT = (BM / 64) * (BN / 32) * 32;
    const int ASZ = BM * STR, BSZ = BN * STR;
    uint32_t sb = smem_u32(sm);
    uint32_t aS[2] = { sb, sb + (uint32_t)(ASZ + BSZ) * 4 };
    uint32_t bS[2] = { sb + (uint32_t)ASZ * 4, sb + (uint32_t)(2 * ASZ + BSZ) * 4 };

    stage_tile<BM, NT>(aS[0], A, lda, 0);
    stage_tile<BN, NT>(bS[0], Bt, ldb, 0);
    CP_COMMIT();

    for (int c = 0; c < nc; c++) {
        if (c + 1 < nc) {
            int nb = (c + 1) & 1;
            stage_tile<BM, NT>(aS[nb], A, lda, (c + 1) * 32);
            stage_tile<BN, NT>(bS[nb], Bt, ldb, (c + 1) * 32);
            CP_COMMIT();
            CP_WAIT1();
        } else {
            CP_WAIT0();
        }
        __syncthreads();
        compute_chunk<BM, BN>(aS[c & 1], bS[c & 1], acc);
        __syncthreads();
    }
}

__device__ __forceinline__ float gelu_exact(float x) {
    return 0.5f * x * (1.f + erff(x * 0.70710678118654752f));
}

enum { EPI_NONE = 0, EPI_BIAS = 1, EPI_BIAS_RES = 2, EPI_BIAS_GELU = 3 };

/* Epilogue directly from accumulators (float2 stores) */
template <int BN, int EPI>
__device__ __forceinline__ void epilogue_dense(float (&acc)[4][4][4],
        float* __restrict__ C, int ldc, int bm, int bn,
        const float* __restrict__ bias, const float* __restrict__ res, int ldres) {
    const int WN = BN / 32;
    int lane = threadIdx.x & 31, wid = threadIdx.x >> 5;
    int wm = wid / WN, wn = wid % WN;
    int r0 = bm + wm * 64 + (lane >> 2);
    int c0 = bn + wn * 32 + 2 * (lane & 3);
    #pragma unroll
    for (int mt = 0; mt < 4; mt++) {
        #pragma unroll
        for (int nt = 0; nt < 4; nt++) {
            int col = c0 + nt * 8;
            float2 bb = make_float2(0.f, 0.f);
            if (EPI >= EPI_BIAS) bb = *(const float2*)(bias + col);
            #pragma unroll
            for (int h = 0; h < 2; h++) {
                int row = r0 + mt * 16 + h * 8;
                float v0 = acc[mt][nt][2 * h], v1 = acc[mt][nt][2 * h + 1];
                if (EPI >= EPI_BIAS) { v0 += bb.x; v1 += bb.y; }
                if (EPI == EPI_BIAS_RES) {
                    float2 rr = *(const float2*)(res + (size_t)row * ldres + col);
                    v0 += rr.x; v1 += rr.y;
                }
                if (EPI == EPI_BIAS_GELU) { v0 = gelu_exact(v0); v1 = gelu_exact(v1); }
                *(float2*)(C + (size_t)row * ldc + col) = make_float2(v0, v1);
            }
        }
    }
}

/* ------------------------------------------------------------------ */
/* Dense GEMM kernel: C[M,N] = A[M,K] * Bt[N,K]^T (+epilogue)          */
/* ------------------------------------------------------------------ */
template <int EPI>
__global__ void __launch_bounds__(256) tc_gemm_k(const float* __restrict__ A, int lda,
        const float* __restrict__ Bt, int ldb, float* __restrict__ C, int ldc, int K,
        const float* __restrict__ bias, const float* __restrict__ res, int ldres) {
    extern __shared__ float sm[];
    int bm = blockIdx.y * 128, bn = blockIdx.x * 128;
    float acc[4][4][4] = {};
    mma_run<128, 128>(sm, A + (size_t)bm * lda, lda, Bt + (size_t)bn * ldb, ldb, K / 32, acc);
    epilogue_dense<128, EPI>(acc, C, ldc, bm, bn, bias, res, ldres);
}

/* ------------------------------------------------------------------ */
/* Attention scores: S = Q K^T / 8 + causal mask                       */
/* ------------------------------------------------------------------ */
__global__ void __launch_bounds__(256) tc_scores_k(const float* __restrict__ qkv,
                                                   float* __restrict__ scores) {
    int kt = blockIdx.x, qt = blockIdx.y, bh = blockIdx.z;
    if (kt > qt) return;
    int b = bh >> 4, h = bh & 15;
    extern __shared__ float sm[];

    const float* Aq = qkv + (size_t)b * SEQ * N3 + (size_t)qt * 128 * N3 + h * DH;
    const float* Bk = qkv + (size_t)b * SEQ * N3 + (size_t)kt * 128 * N3 + D_RES + h * DH;
    float acc[4][4][4] = {};
    mma_run<128, 128>(sm, Aq, N3, Bk, N3, DH / 32, acc);

    float* out = scores + (size_t)bh * SEQ * SEQ;
    int lane = threadIdx.x & 31, wid = threadIdx.x >> 5;
    int wm = wid >> 2, wn = wid & 3;
    int r0 = qt * 128 + wm * 64 + (lane >> 2);
    int c0 = kt * 128 + wn * 32 + 2 * (lane & 3);
    bool diag = (kt == qt);
    #pragma unroll
    for (int mt = 0; mt < 4; mt++) {
        #pragma unroll
        for (int nt = 0; nt < 4; nt++) {
            int col = c0 + nt * 8;
            #pragma unroll
            for (int hh = 0; hh < 2; hh++) {
                int row = r0 + mt * 16 + hh * 8;
                float v0 = acc[mt][nt][2 * hh] * 0.125f;
                float v1 = acc[mt][nt][2 * hh + 1] * 0.125f;
                if (diag) {
                    if (col > row)     v0 = IGNORE_VAL;
                    if (col + 1 > row) v1 = IGNORE_VAL;
                }
                *(float2*)(out + (size_t)row * SEQ + col) = make_float2(v0, v1);
            }
        }
    }
}

/* ------------------------------------------------------------------ */
/* PV: Z = P V (BN=64, causal K limit)                                 */
/* ------------------------------------------------------------------ */
__global__ void __launch_bounds__(128) tc_pv_k(const float* __restrict__ scores,
                                               const float* __restrict__ vt,
                                               float* __restrict__ Z) {
    int qt = blockIdx.y, bh = blockIdx.z;
    int b = bh >> 4, h = bh & 15;
    int bm = qt * 128;
    extern __shared__ float sm[];

    const float* A = scores + (size_t)bh * SEQ * SEQ + (size_t)bm * SEQ;
    const float* B = vt + (size_t)bh * DH * SEQ;
    float acc[4][4][4] = {};
    mma_run<128, 64>(sm, A, SEQ, B, SEQ, (bm + 128) / 32, acc);

    float* C = Z + (size_t)b * SEQ * D_RES + h * DH;
    epilogue_dense<64, EPI_NONE>(acc, C, D_RES, bm, 0, nullptr, nullptr, 0);
}

/* ------------------------------------------------------------------ */
/* LayerNorm                                                           */
/* ------------------------------------------------------------------ */
__global__ void layernorm_k(const float* __restrict__ in, const float* __restrict__ w,
                            const float* __restrict__ b, float* __restrict__ out) {
    int row = blockIdx.x;
    const float* x = in + (size_t)row * D_RES;
    float* o = out + (size_t)row * D_RES;
    __shared__ float red[256];
    int t = threadIdx.x;

    float s = 0.f;
    for (int i = t; i < D_RES; i += 256) s += x[i];
    red[t] = s; __syncthreads();
    for (int k = 128; k > 0; k >>= 1) { if (t < k) red[t] += red[t + k]; __syncthreads(); }
    float mean = red[0] * (1.f / D_RES);
    __syncthreads();

    float v = 0.f;
    for (int i = t; i < D_RES; i += 256) { float c = x[i] - mean; v += c * c; }
    red[t] = v; __syncthreads();
    for (int k = 128; k > 0; k >>= 1) { if (t < k) red[t] += red[t + k]; __syncthreads(); }
    float inv = rsqrtf(red[0] * (1.f / D_RES) + EPSLN);

    for (int i = t; i < D_RES; i += 256)
        o[i] = (x[i] - mean) * inv * w[i] + b[i];
}

/* ------------------------------------------------------------------ */
/* Softmax (causal) — zero-fills to the 128 boundary for PV            */
/* ------------------------------------------------------------------ */
__global__ void softmax_k(float* __restrict__ scores) {
    int s  = blockIdx.x;
    int bh = blockIdx.y;
    float* row = scores + (size_t)bh * SEQ * SEQ + (size_t)s * SEQ;
    int n = s + 1;

    __shared__ float srow[SEQ];
    __shared__ float red[256];
    int t = threadIdx.x;

    float mx = -3.0e38f;
    for (int i = t; i < n; i += 256) { float v = row[i]; srow[i] = v; mx = fmaxf(mx, v); }
    red[t] = mx; __syncthreads();
    for (int k = 128; k > 0; k >>= 1) { if (t < k) red[t] = fmaxf(red[t], red[t + k]); __syncthreads(); }
    mx = red[0]; __syncthreads();

    float ss = 0.f;
    for (int i = t; i < n; i += 256) { float e = expf(srow[i] - mx); srow[i] = e; ss += e; }
    red[t] = ss; __syncthreads();
    for (int k = 128; k > 0; k >>= 1) { if (t < k) red[t] += red[t + k]; __syncthreads(); }
    float inv = 1.f / red[0];

    for (int i = t; i < n; i += 256) row[i] = srow[i] * inv;
    int lim = ((s >> 7) + 1) << 7;
    for (int i = n + t; i < lim; i += 256) row[i] = 0.f;
}

/* ------------------------------------------------------------------ */
/* Weight packing / transposes                                         */
/* ------------------------------------------------------------------ */
__global__ void pack_qkv_k(const float* __restrict__ WQ, const float* __restrict__ WK,
                           const float* __restrict__ WV, const float* __restrict__ bQ,
                           const float* __restrict__ bK, const float* __restrict__ bV) {
    int idx = blockIdx.x * blockDim.x + threadIdx.x;
    if (idx < N3 * D_RES) {
        int n = idx / D_RES;           /* output row: sel*1024 + h*64 + e */
        int d = idx % D_RES;
        int sel = n / D_RES;
        int c = n % D_RES;
        int h = c / DH, e = c % DH;
        const float* W = (sel == 0) ? WQ : (sel == 1) ? WK : WV;
        g_Wqkv_t[idx] = W[((size_t)h * D_RES + d) * DH + e];
    }
    if (idx < N3) {
        const float* bb = (idx < D_RES) ? bQ : (idx < 2 * D_RES) ? bK : bV;
        g_bias_qkv[idx] = bb[idx % D_RES];
    }
}

/* out[C][R] = in[R][C]^T */
__global__ void transpose_k(const float* __restrict__ in, float* __restrict__ out,
                            int R, int C) {
    __shared__ float tile[32][33];
    int c0 = blockIdx.x * 32, r0 = blockIdx.y * 32;
    for (int i = threadIdx.y; i < 32; i += 8)
        tile[i][threadIdx.x] = in[(size_t)(r0 + i) * C + c0 + threadIdx.x];
    __syncthreads();
    for (int i = threadIdx.y; i < 32; i += 8)
        out[(size_t)(c0 + i) * R + r0 + threadIdx.x] = tile[threadIdx.x][i];
}

/* vt[bh][e][k] = qkv[b][k][2048 + h*64 + e] */
__global__ void vtrans_k(const float* __restrict__ qkv, float* __restrict__ vt) {
    __shared__ float tile[32][33];
    int bh = blockIdx.z, b = bh >> 4, h = bh & 15;
    const float* src = qkv + (size_t)b * SEQ * N3 + 2 * D_RES + h * DH;
    int k0 = blockIdx.x * 32, e0 = blockIdx.y * 32;
    for (int i = threadIdx.y; i < 32; i += 8)
        tile[i][threadIdx.x] = src[(size_t)(k0 + i) * N3 + e0 + threadIdx.x];
    __syncthreads();
    float* dst = vt + (size_t)bh * DH * SEQ;
    for (int i = threadIdx.y; i < 32; i += 8)
        dst[(size_t)(e0 + i) * SEQ + k0 + threadIdx.x] = tile[threadIdx.x][i];
}

/* ------------------------------------------------------------------ */
/* Launch                                                              */
/* ------------------------------------------------------------------ */
#define SMEM_128_128 (2 * (128 * STR + 128 * STR) * 4)   /* 73728 */
#define SMEM_128_64  (2 * (128 * STR + 64 * STR) * 4)    /* 55296 */

extern "C" void kernel_launch(void* const* d_in, const int* in_sizes, int n_in,
                              void* d_out, int out_size) {
    const float* resid_pre = (const float*)d_in[0];
    const float* ln1_w = (const float*)d_in[1];
    const float* ln1_b = (const float*)d_in[2];
    const float* WQ = (const float*)d_in[3];
    const float* bQ = (const float*)d_in[4];
    const float* WK = (const float*)d_in[5];
    const float* bK = (const float*)d_in[6];
    const float* WV = (const float*)d_in[7];
    const float* bV = (const float*)d_in[8];
    const float* WO = (const float*)d_in[9];
    const float* bO = (const float*)d_in[10];
    const float* ln2_w = (const float*)d_in[11];
    const float* ln2_b = (const float*)d_in[12];
    const float* Win  = (const float*)d_in[13];
    const float* bin  = (const float*)d_in[14];
    const float* Wout = (const float*)d_in[15];
    const float* bout = (const float*)d_in[16];
    float* out = (float*)d_out;

    float *p_Wqkvt, *p_bias, *p_WOt, *p_Wint, *p_Woutt, *p_xln, *p_qkv, *p_vt,
          *p_scores, *p_z, *p_mid, *p_y, *p_post;
    cudaGetSymbolAddress((void**)&p_Wqkvt, g_Wqkv_t);
    cudaGetSymbolAddress((void**)&p_bias, g_bias_qkv);
    cudaGetSymbolAddress((void**)&p_WOt, g_WOt);
    cudaGetSymbolAddress((void**)&p_Wint, g_Wint);
    cudaGetSymbolAddress((void**)&p_Woutt, g_Woutt);
    cudaGetSymbolAddress((void**)&p_xln, g_xln);
    cudaGetSymbolAddress((void**)&p_qkv, g_qkv);
    cudaGetSymbolAddress((void**)&p_vt, g_vt);
    cudaGetSymbolAddress((void**)&p_scores, g_scores);
    cudaGetSymbolAddress((void**)&p_z, g_z);
    cudaGetSymbolAddress((void**)&p_mid, g_resid_mid);
    cudaGetSymbolAddress((void**)&p_y, g_y);
    cudaGetSymbolAddress((void**)&p_post, g_post);

    cudaFuncSetAttribute(tc_gemm_k<EPI_BIAS>,
                         cudaFuncAttributeMaxDynamicSharedMemorySize, SMEM_128_128);
    cudaFuncSetAttribute(tc_gemm_k<EPI_BIAS_RES>,
                         cudaFuncAttributeMaxDynamicSharedMemorySize, SMEM_128_128);
    cudaFuncSetAttribute(tc_gemm_k<EPI_BIAS_GELU>,
                         cudaFuncAttributeMaxDynamicSharedMemorySize, SMEM_128_128);
    cudaFuncSetAttribute(tc_scores_k,
                         cudaFuncAttributeMaxDynamicSharedMemorySize, SMEM_128_128);
    cudaFuncSetAttribute(tc_pv_k,
                         cudaFuncAttributeMaxDynamicSharedMemorySize, SMEM_128_64);

    /* weight prep */
    pack_qkv_k<<<(N3 * D_RES + 255) / 256, 256>>>(WQ, WK, WV, bQ, bK, bV);
    transpose_k<<<dim3(32, 32), dim3(32, 8)>>>(WO, p_WOt, D_RES, D_RES);
    transpose_k<<<dim3(128, 32), dim3(32, 8)>>>(Win, p_Wint, D_RES, DMLP);
    transpose_k<<<dim3(32, 128), dim3(32, 8)>>>(Wout, p_Woutt, DMLP, D_RES);

    /* LN1 */
    layernorm_k<<<NTOK, 256>>>(resid_pre, ln1_w, ln1_b, p_xln);

    /* QKV = xln @ Wqkv + bias */
    tc_gemm_k<EPI_BIAS><<<dim3(N3 / 128, NTOK / 128), 256, SMEM_128_128>>>(
        p_xln, D_RES, p_Wqkvt, D_RES, p_qkv, N3, D_RES, p_bias, nullptr, 0);

    /* V^T per head */
    vtrans_k<<<dim3(SEQ / 32, DH / 32, BATCH * NH), dim3(32, 8)>>>(p_qkv, p_vt);

    /* scores = Q K^T / 8 + causal mask */
    tc_scores_k<<<dim3(SEQ / 128, SEQ / 128, BATCH * NH), 256, SMEM_128_128>>>(p_qkv, p_scores);

    /* softmax */
    softmax_k<<<dim3(SEQ, BATCH * NH), 256>>>(p_scores);

    /* Z = P V */
    tc_pv_k<<<dim3(1, SEQ / 128, BATCH * NH), 128, SMEM_128_64>>>(p_scores, p_vt, p_z);

    /* resid_mid = Z @ W_O + b_O + resid_pre */
    tc_gemm_k<EPI_BIAS_RES><<<dim3(D_RES / 128, NTOK / 128), 256, SMEM_128_128>>>(
        p_z, D_RES, p_WOt, D_RES, p_mid, D_RES, D_RES, bO, resid_pre, D_RES);

    /* LN2 */
    layernorm_k<<<NTOK, 256>>>(p_mid, ln2_w, ln2_b, p_y);

    /* post = gelu(y @ W_in + b_in) */
    tc_gemm_k<EPI_BIAS_GELU><<<dim3(DMLP / 128, NTOK / 128), 256, SMEM_128_128>>>(
        p_y, D_RES, p_Wint, D_RES, p_post, DMLP, D_RES, bin, nullptr, 0);

    /* out = post @ W_out + b_out + resid_mid */
    tc_gemm_k<EPI_BIAS_RES><<<dim3(D_RES / 128, NTOK / 128), 256, SMEM_128_128>>>(
        p_post, DMLP, p_Woutt, DMLP, out, D_RES, DMLP, bout, p_mid, D_RES);
}

// round 7
// speedup vs baseline: 3.5124x; 1.3120x over previous
#include <cuda_runtime.h>
#include <math.h>
#include <stdint.h>

#define D_RES  1024
#define NH     16
#define DH     64
#define DMLP   4096
#define SEQ    2048
#define BATCH  2
#define NTOK   (BATCH*SEQ)      /* 4096 */
#define N3     (3*D_RES)        /* 3072 */
#define EPSLN  1e-5f

/* ------------------------------------------------------------------ */
/* Scratch: __device__ globals                                         */
/* ------------------------------------------------------------------ */
__device__ float g_Wqkv_t[N3 * D_RES];               /* 12 MB  [3072][1024] */
__device__ float g_bias_qkv[N3];
__device__ float g_WOt[D_RES * D_RES];               /*  4 MB */
__device__ float g_Wint[DMLP * D_RES];               /* 16 MB */
__device__ float g_Woutt[D_RES * DMLP];              /* 16 MB */
__device__ float g_xln[(size_t)NTOK * D_RES];        /* 16 MB */
__device__ float g_qkv[(size_t)NTOK * N3];           /* 48 MB */
__device__ float g_vt[(size_t)BATCH * NH * DH * SEQ];/* 16 MB  [bh][e][k] */
__device__ float g_z[(size_t)NTOK * D_RES];          /* 16 MB */
__device__ float g_resid_mid[(size_t)NTOK * D_RES];  /* 16 MB */
__device__ float g_y[(size_t)NTOK * D_RES];          /* 16 MB */
__device__ float g_post[(size_t)NTOK * DMLP];        /* 64 MB */

/* ------------------------------------------------------------------ */
/* PTX helpers (sm_103 base ISA: cp.async + ldmatrix + mma.sync tf32)  */
/* ------------------------------------------------------------------ */
__device__ __forceinline__ uint32_t smem_u32(const void* p) {
    uint32_t a;
    asm("{ .reg .u64 t; cvta.to.shared.u64 t, %1; cvt.u32.u64 %0, t; }" : "=r"(a) : "l"(p));
    return a;
}
__device__ __forceinline__ void cp16(uint32_t dst, const float* src) {
    asm volatile("cp.async.ca.shared.global [%0], [%1], 16;" :: "r"(dst), "l"(src));
}
#define CP_COMMIT()  asm volatile("cp.async.commit_group;" ::: "memory")
#define CP_WAIT0()   asm volatile("cp.async.wait_group 0;" ::: "memory")
#define CP_WAIT1()   asm volatile("cp.async.wait_group 1;" ::: "memory")

__device__ __forceinline__ void ldsm4(uint32_t a, uint32_t& r0, uint32_t& r1,
                                      uint32_t& r2, uint32_t& r3) {
    asm volatile("ldmatrix.sync.aligned.m8n8.x4.shared.b16 {%0,%1,%2,%3}, [%4];"
                 : "=r"(r0), "=r"(r1), "=r"(r2), "=r"(r3) : "r"(a));
}
__device__ __forceinline__ void cvt_tf32(uint32_t& x) {
    asm("cvt.rna.tf32.f32 %0, %0;" : "+r"(x));
}
__device__ __forceinline__ void mma_tf32(float* c, const uint32_t* a,
                                         uint32_t b0, uint32_t b1) {
    asm volatile("mma.sync.aligned.m16n8k8.row.col.f32.tf32.tf32.f32 "
                 "{%0,%1,%2,%3}, {%4,%5,%6,%7}, {%8,%9}, {%0,%1,%2,%3};"
                 : "+f"(c[0]), "+f"(c[1]), "+f"(c[2]), "+f"(c[3])
                 : "r"(a[0]), "r"(a[1]), "r"(a[2]), "r"(a[3]), "r"(b0), "r"(b1));
}

/* ------------------------------------------------------------------ */
/* Warp-MMA core. K-chunk 32. SMEM rows: 36 floats (144 B).            */
/* ------------------------------------------------------------------ */
#define STR 36

template <int ROWS, int NT>
__device__ __forceinline__ void stage_tile(uint32_t s, const float* __restrict__ g,
                                           int ld, int k0) {
    #pragma unroll
    for (int i = 0; i < (ROWS * 8) / NT; i++) {
        int u = threadIdx.x + i * NT;
        int r = u >> 3, c = u & 7;
        cp16(s + (uint32_t)(r * STR + c * 4) * 4, g + (size_t)r * ld + k0 + c * 4);
    }
}

/* Warp grid: wm = wid/WN, wn = wid%WN. Warp tile (MT*16) x (NT*8).    */
template <int MT, int NT, int WN>
__device__ __forceinline__ void compute_chunk(uint32_t a_s, uint32_t b_s,
                                              float (&acc)[MT][NT][4]) {
    int lane = threadIdx.x & 31, wid = threadIdx.x >> 5;
    int wm = wid / WN, wn = wid % WN;
    uint32_t ab = a_s + (uint32_t)(((wm * (MT * 16) + (lane & 15)) * STR
                                    + ((lane >> 4) << 2)) * 4);
    uint32_t bb = b_s + (uint32_t)(((wn * (NT * 8) + (lane & 7) + ((lane >> 4) << 3)) * STR
                                    + (((lane >> 3) & 1) << 2)) * 4);
    #pragma unroll
    for (int ks = 0; ks < 4; ks++) {
        uint32_t af[MT][4], bf[NT][2];
        #pragma unroll
        for (int mt = 0; mt < MT; mt++)
            ldsm4(ab + mt * (16 * STR * 4) + ks * 32,
                  af[mt][0], af[mt][1], af[mt][2], af[mt][3]);
        #pragma unroll
        for (int p = 0; p < NT / 2; p++)
            ldsm4(bb + p * (16 * STR * 4) + ks * 32,
                  bf[2 * p][0], bf[2 * p][1], bf[2 * p + 1][0], bf[2 * p + 1][1]);
        #pragma unroll
        for (int mt = 0; mt < MT; mt++)
            #pragma unroll
            for (int j = 0; j < 4; j++) cvt_tf32(af[mt][j]);
        #pragma unroll
        for (int nt = 0; nt < NT; nt++) { cvt_tf32(bf[nt][0]); cvt_tf32(bf[nt][1]); }
        #pragma unroll
        for (int mt = 0; mt < MT; mt++)
            #pragma unroll
            for (int nt = 0; nt < NT; nt++)
                mma_tf32(acc[mt][nt], af[mt], bf[nt][0], bf[nt][1]);
    }
}

/* Dense pipelined K loop (BM=BN=128, 8 warps) */
__device__ __forceinline__ void mma_run_dense(float* sm,
        const float* __restrict__ A, int lda,
        const float* __restrict__ Bt, int ldb, int nc, float (&acc)[4][4][4]) {
    const int ASZ = 128 * STR, BSZ = 128 * STR;
    uint32_t sb = smem_u32(sm);
    uint32_t aS[2] = { sb, sb + (uint32_t)(ASZ + BSZ) * 4 };
    uint32_t bS[2] = { sb + (uint32_t)ASZ * 4, sb + (uint32_t)(2 * ASZ + BSZ) * 4 };

    stage_tile<128, 256>(aS[0], A, lda, 0);
    stage_tile<128, 256>(bS[0], Bt, ldb, 0);
    CP_COMMIT();

    for (int c = 0; c < nc; c++) {
        if (c + 1 < nc) {
            int nb = (c + 1) & 1;
            stage_tile<128, 256>(aS[nb], A, lda, (c + 1) * 32);
            stage_tile<128, 256>(bS[nb], Bt, ldb, (c + 1) * 32);
            CP_COMMIT();
            CP_WAIT1();
        } else {
            CP_WAIT0();
        }
        __syncthreads();
        compute_chunk<4, 4, 4>(aS[c & 1], bS[c & 1], acc);
        __syncthreads();
    }
}

__device__ __forceinline__ float gelu_exact(float x) {
    return 0.5f * x * (1.f + erff(x * 0.70710678118654752f));
}

enum { EPI_NONE = 0, EPI_BIAS = 1, EPI_BIAS_RES = 2, EPI_BIAS_GELU = 3 };

template <int EPI>
__device__ __forceinline__ void epilogue_dense(float (&acc)[4][4][4],
        float* __restrict__ C, int ldc, int bm, int bn,
        const float* __restrict__ bias, const float* __restrict__ res, int ldres) {
    int lane = threadIdx.x & 31, wid = threadIdx.x >> 5;
    int wm = wid >> 2, wn = wid & 3;
    int r0 = bm + wm * 64 + (lane >> 2);
    int c0 = bn + wn * 32 + 2 * (lane & 3);
    #pragma unroll
    for (int mt = 0; mt < 4; mt++) {
        #pragma unroll
        for (int nt = 0; nt < 4; nt++) {
            int col = c0 + nt * 8;
            float2 bb = make_float2(0.f, 0.f);
            if (EPI >= EPI_BIAS) bb = *(const float2*)(bias + col);
            #pragma unroll
            for (int h = 0; h < 2; h++) {
                int row = r0 + mt * 16 + h * 8;
                float v0 = acc[mt][nt][2 * h], v1 = acc[mt][nt][2 * h + 1];
                if (EPI >= EPI_BIAS) { v0 += bb.x; v1 += bb.y; }
                if (EPI == EPI_BIAS_RES) {
                    float2 rr = *(const float2*)(res + (size_t)row * ldres + col);
                    v0 += rr.x; v1 += rr.y;
                }
                if (EPI == EPI_BIAS_GELU) { v0 = gelu_exact(v0); v1 = gelu_exact(v1); }
                *(float2*)(C + (size_t)row * ldc + col) = make_float2(v0, v1);
            }
        }
    }
}

/* ------------------------------------------------------------------ */
/* Dense GEMM kernel                                                   */
/* ------------------------------------------------------------------ */
template <int EPI>
__global__ void __launch_bounds__(256) tc_gemm_k(const float* __restrict__ A, int lda,
        const float* __restrict__ Bt, int ldb, float* __restrict__ C, int ldc, int K,
        const float* __restrict__ bias, const float* __restrict__ res, int ldres) {
    extern __shared__ float sm[];
    int bm = blockIdx.y * 128, bn = blockIdx.x * 128;
    float acc[4][4][4] = {};
    mma_run_dense(sm, A + (size_t)bm * lda, lda, Bt + (size_t)bn * ldb, ldb, K / 32, acc);
    epilogue_dense<EPI>(acc, C, ldc, bm, bn, bias, res, ldres);
}

/* ------------------------------------------------------------------ */
/* Flash attention: per (bh, q-tile 128): S=QK^T/8 causal, online      */
/* softmax, O = P V. CTAs paired {x, 15-x} for perfect balance.        */
/* SMEM (floats): Q[2][128][36] K[2][128][36] V[4][64][36]             */
/*                P[4][128][36] rowred[128][4]                         */
/* ------------------------------------------------------------------ */
#define FO_Q   0
#define FO_K   (2 * 128 * STR)
#define FO_V   (FO_K + 2 * 128 * STR)
#define FO_P   (FO_V + 4 * 64 * STR)
#define FO_RED (FO_P + 4 * 128 * STR)
#define FLASH_SMEM ((FO_RED + 128 * 4) * 4)

__global__ void __launch_bounds__(256) flash_k(const float* __restrict__ qkv,
                                               const float* __restrict__ vt,
                                               float* __restrict__ Z) {
    extern __shared__ float sm[];
    uint32_t sb = smem_u32(sm);
    const uint32_t sQ = sb + FO_Q * 4;
    const uint32_t sK = sb + FO_K * 4;
    const uint32_t sV = sb + FO_V * 4;
    const uint32_t sP = sb + FO_P * 4;
    float* rowred = sm + FO_RED;

    int bh = blockIdx.y, b = bh >> 4, h = bh & 15;
    int lane = threadIdx.x & 31, wid = threadIdx.x >> 5;
    int wm = wid >> 2, wn = wid & 3;

    const float* qbase = qkv + (size_t)b * SEQ * N3 + h * DH;
    const float* kbase = qbase + D_RES;
    const float* vtb = vt + (size_t)bh * DH * SEQ;
    float* Zb = Z + (size_t)b * SEQ * D_RES + h * DH;

    #pragma unroll 1
    for (int half = 0; half < 2; half++) {
        int qt = half ? (15 - (int)blockIdx.x) : (int)blockIdx.x;

        /* stage Q tile (2 chunks) */
        #pragma unroll
        for (int c = 0; c < 2; c++)
            stage_tile<128, 256>(sQ + c * (128 * STR * 4),
                                 qbase + (size_t)qt * 128 * N3, N3, c * 32);
        CP_COMMIT();

        float m_i[8], l_i[8];
        float oacc[4][2][4] = {};
        #pragma unroll
        for (int s = 0; s < 8; s++) { m_i[s] = -1e30f; l_i[s] = 0.f; }

        for (int kt = 0; kt <= qt; kt++) {
            /* stage K (2 chunks) + V (4 chunks) */
            #pragma unroll
            for (int c = 0; c < 2; c++)
                stage_tile<128, 256>(sK + c * (128 * STR * 4),
                                     kbase + (size_t)kt * 128 * N3, N3, c * 32);
            #pragma unroll
            for (int c = 0; c < 4; c++)
                stage_tile<64, 256>(sV + c * (64 * STR * 4), vtb, SEQ,
                                    kt * 128 + c * 32);
            CP_COMMIT();
            CP_WAIT0();
            __syncthreads();

            /* S = Q K^T */
            float sacc[4][4][4] = {};
            compute_chunk<4, 4, 4>(sQ, sK, sacc);
            compute_chunk<4, 4, 4>(sQ + 128 * STR * 4, sK + 128 * STR * 4, sacc);

            /* scale + causal mask (registers) */
            int rl0 = wm * 64 + (lane >> 2);
            int cl0 = wn * 32 + 2 * (lane & 3);
            bool diag = (kt == qt);
            #pragma unroll
            for (int mt = 0; mt < 4; mt++)
                #pragma unroll
                for (int nt = 0; nt < 4; nt++)
                    #pragma unroll
                    for (int hh = 0; hh < 2; hh++) {
                        int r = rl0 + mt * 16 + 8 * hh;
                        int c = cl0 + nt * 8;
                        float v0 = sacc[mt][nt][2 * hh] * 0.125f;
                        float v1 = sacc[mt][nt][2 * hh + 1] * 0.125f;
                        if (diag) {
                            if (c > r)     v0 = -1e30f;
                            if (c + 1 > r) v1 = -1e30f;
                        }
                        sacc[mt][nt][2 * hh] = v0;
                        sacc[mt][nt][2 * hh + 1] = v1;
                    }

            /* row-max: quad shfl + cross-warp smem */
            #pragma unroll
            for (int mt = 0; mt < 4; mt++)
                #pragma unroll
                for (int hh = 0; hh < 2; hh++) {
                    float v = -1e30f;
                    #pragma unroll
                    for (int nt = 0; nt < 4; nt++) {
                        v = fmaxf(v, sacc[mt][nt][2 * hh]);
                        v = fmaxf(v, sacc[mt][nt][2 * hh + 1]);
                    }
                    v = fmaxf(v, __shfl_xor_sync(0xffffffffu, v, 1));
                    v = fmaxf(v, __shfl_xor_sync(0xffffffffu, v, 2));
                    if ((lane & 3) == 0)
                        rowred[(rl0 + mt * 16 + 8 * hh) * 4 + wn] = v;
                }
            __syncthreads();
            float m_new[8], alpha[8];
            #pragma unroll
            for (int mt = 0; mt < 4; mt++)
                #pragma unroll
                for (int hh = 0; hh < 2; hh++) {
                    int s = mt * 2 + hh;
                    const float* rr = rowred + (rl0 + mt * 16 + 8 * hh) * 4;
                    float tm = fmaxf(fmaxf(rr[0], rr[1]), fmaxf(rr[2], rr[3]));
                    m_new[s] = fmaxf(m_i[s], tm);
                    alpha[s] = __expf(m_i[s] - m_new[s]);
                    m_i[s] = m_new[s];
                }
            __syncthreads();

            /* P = exp(S - m), partial row sums, store P to smem */
            #pragma unroll
            for (int mt = 0; mt < 4; mt++)
                #pragma unroll
                for (int hh = 0; hh < 2; hh++) {
                    int s = mt * 2 + hh;
                    float ps = 0.f;
                    uint32_t prow = sP + (uint32_t)(((wn * 128) + rl0 + mt * 16 + 8 * hh)
                                                    * STR) * 4;
                    #pragma unroll
                    for (int nt = 0; nt < 4; nt++) {
                        float p0 = __expf(sacc[mt][nt][2 * hh] - m_new[s]);
                        float p1 = __expf(sacc[mt][nt][2 * hh + 1] - m_new[s]);
                        ps += p0 + p1;
                        asm volatile("st.shared.v2.f32 [%0], {%1, %2};"
                                     :: "r"(prow + (uint32_t)((nt * 8 + 2 * (lane & 3)) * 4)),
                                        "f"(p0), "f"(p1));
                    }
                    ps += __shfl_xor_sync(0xffffffffu, ps, 1);
                    ps += __shfl_xor_sync(0xffffffffu, ps, 2);
                    if ((lane & 3) == 0)
                        rowred[(rl0 + mt * 16 + 8 * hh) * 4 + wn] = ps;
                }
            __syncthreads();
            #pragma unroll
            for (int mt = 0; mt < 4; mt++)
                #pragma unroll
                for (int hh = 0; hh < 2; hh++) {
                    int s = mt * 2 + hh;
                    const float* rr = rowred + (rl0 + mt * 16 + 8 * hh) * 4;
                    l_i[s] = l_i[s] * alpha[s] + (rr[0] + rr[1] + rr[2] + rr[3]);
                    /* rescale O accumulators */
                    #pragma unroll
                    for (int nt = 0; nt < 2; nt++) {
                        oacc[mt][nt][2 * hh]     *= alpha[s];
                        oacc[mt][nt][2 * hh + 1] *= alpha[s];
                    }
                }

            /* O += P V  (4 K-chunks of 32) */
            #pragma unroll
            for (int c = 0; c < 4; c++)
                compute_chunk<4, 2, 4>(sP + c * (128 * STR * 4),
                                       sV + c * (64 * STR * 4), oacc);
            __syncthreads();
        }

        /* write O = oacc / l */
        #pragma unroll
        for (int mt = 0; mt < 4; mt++)
            #pragma unroll
            for (int hh = 0; hh < 2; hh++) {
                int s = mt * 2 + hh;
                float inv = 1.f / l_i[s];
                int row = qt * 128 + wm * 64 + mt * 16 + (lane >> 2) + 8 * hh;
                #pragma unroll
                for (int nt = 0; nt < 2; nt++) {
                    int col = wn * 16 + nt * 8 + 2 * (lane & 3);
                    *(float2*)(Zb + (size_t)row * D_RES + col) =
                        make_float2(oacc[mt][nt][2 * hh] * inv,
                                    oacc[mt][nt][2 * hh + 1] * inv);
                }
            }
        __syncthreads();
    }
}

/* ------------------------------------------------------------------ */
/* LayerNorm: single pass, 4 elems/thread in registers                 */
/* ------------------------------------------------------------------ */
__global__ void __launch_bounds__(256) layernorm_k(const float* __restrict__ in,
        const float* __restrict__ w, const float* __restrict__ b,
        float* __restrict__ out) {
    int row = blockIdx.x, t = threadIdx.x;
    const float* x = in + (size_t)row * D_RES;
    float4 v = *(const float4*)(x + t * 4);
    float s = v.x + v.y + v.z + v.w;
    float q = v.x * v.x + v.y * v.y + v.z * v.z + v.w * v.w;
    #pragma unroll
    for (int o = 16; o > 0; o >>= 1) {
        s += __shfl_xor_sync(0xffffffffu, s, o);
        q += __shfl_xor_sync(0xffffffffu, q, o);
    }
    __shared__ float rs[8], rq[8];
    int wid = t >> 5;
    if ((t & 31) == 0) { rs[wid] = s; rq[wid] = q; }
    __syncthreads();
    s = rs[0] + rs[1] + rs[2] + rs[3] + rs[4] + rs[5] + rs[6] + rs[7];
    q = rq[0] + rq[1] + rq[2] + rq[3] + rq[4] + rq[5] + rq[6] + rq[7];
    float mean = s * (1.f / D_RES);
    float inv = rsqrtf(q * (1.f / D_RES) - mean * mean + EPSLN);
    float4 wv = *(const float4*)(w + t * 4);
    float4 bv = *(const float4*)(b + t * 4);
    float4 o;
    o.x = (v.x - mean) * inv * wv.x + bv.x;
    o.y = (v.y - mean) * inv * wv.y + bv.y;
    o.z = (v.z - mean) * inv * wv.z + bv.z;
    o.w = (v.w - mean) * inv * wv.w + bv.w;
    *(float4*)(out + (size_t)row * D_RES + t * 4) = o;
}

/* ------------------------------------------------------------------ */
/* Weight packing / transposes                                         */
/* ------------------------------------------------------------------ */
__global__ void pack_qkv_k(const float* __restrict__ WQ, const float* __restrict__ WK,
                           const float* __restrict__ WV, const float* __restrict__ bQ,
                           const float* __restrict__ bK, const float* __restrict__ bV) {
    int idx = blockIdx.x * blockDim.x + threadIdx.x;
    if (idx < N3 * D_RES) {
        int n = idx / D_RES;
        int d = idx % D_RES;
        int sel = n / D_RES;
        int c = n % D_RES;
        int h = c / DH, e = c % DH;
        const float* W = (sel == 0) ? WQ : (sel == 1) ? WK : WV;
        g_Wqkv_t[idx] = W[((size_t)h * D_RES + d) * DH + e];
    }
    if (idx < N3) {
        const float* bb = (idx < D_RES) ? bQ : (idx < 2 * D_RES) ? bK : bV;
        g_bias_qkv[idx] = bb[idx % D_RES];
    }
}

__global__ void transpose_k(const float* __restrict__ in, float* __restrict__ out,
                            int R, int C) {
    __shared__ float tile[32][33];
    int c0 = blockIdx.x * 32, r0 = blockIdx.y * 32;
    for (int i = threadIdx.y; i < 32; i += 8)
        tile[i][threadIdx.x] = in[(size_t)(r0 + i) * C + c0 + threadIdx.x];
    __syncthreads();
    for (int i = threadIdx.y; i < 32; i += 8)
        out[(size_t)(c0 + i) * R + r0 + threadIdx.x] = tile[threadIdx.x][i];
}

/* vt[bh][e][k] = qkv[b][k][2048 + h*64 + e] */
__global__ void vtrans_k(const float* __restrict__ qkv, float* __restrict__ vt) {
    __shared__ float tile[32][33];
    int bh = blockIdx.z, b = bh >> 4, h = bh & 15;
    const float* src = qkv + (size_t)b * SEQ * N3 + 2 * D_RES + h * DH;
    int k0 = blockIdx.x * 32, e0 = blockIdx.y * 32;
    for (int i = threadIdx.y; i < 32; i += 8)
        tile[i][threadIdx.x] = src[(size_t)(k0 + i) * N3 + e0 + threadIdx.x];
    __syncthreads();
    float* dst = vt + (size_t)bh * DH * SEQ;
    for (int i = threadIdx.y; i < 32; i += 8)
        dst[(size_t)(e0 + i) * SEQ + k0 + threadIdx.x] = tile[threadIdx.x][i];
}

/* ------------------------------------------------------------------ */
/* Launch                                                              */
/* ------------------------------------------------------------------ */
#define SMEM_128_128 (2 * (128 * STR + 128 * STR) * 4)   /* 73728 */

extern "C" void kernel_launch(void* const* d_in, const int* in_sizes, int n_in,
                              void* d_out, int out_size) {
    const float* resid_pre = (const float*)d_in[0];
    const float* ln1_w = (const float*)d_in[1];
    const float* ln1_b = (const float*)d_in[2];
    const float* WQ = (const float*)d_in[3];
    const float* bQ = (const float*)d_in[4];
    const float* WK = (const float*)d_in[5];
    const float* bK = (const float*)d_in[6];
    const float* WV = (const float*)d_in[7];
    const float* bV = (const float*)d_in[8];
    const float* WO = (const float*)d_in[9];
    const float* bO = (const float*)d_in[10];
    const float* ln2_w = (const float*)d_in[11];
    const float* ln2_b = (const float*)d_in[12];
    const float* Win  = (const float*)d_in[13];
    const float* bin  = (const float*)d_in[14];
    const float* Wout = (const float*)d_in[15];
    const float* bout = (const float*)d_in[16];
    float* out = (float*)d_out;

    float *p_Wqkvt, *p_bias, *p_WOt, *p_Wint, *p_Woutt, *p_xln, *p_qkv, *p_vt,
          *p_z, *p_mid, *p_y, *p_post;
    cudaGetSymbolAddress((void**)&p_Wqkvt, g_Wqkv_t);
    cudaGetSymbolAddress((void**)&p_bias, g_bias_qkv);
    cudaGetSymbolAddress((void**)&p_WOt, g_WOt);
    cudaGetSymbolAddress((void**)&p_Wint, g_Wint);
    cudaGetSymbolAddress((void**)&p_Woutt, g_Woutt);
    cudaGetSymbolAddress((void**)&p_xln, g_xln);
    cudaGetSymbolAddress((void**)&p_qkv, g_qkv);
    cudaGetSymbolAddress((void**)&p_vt, g_vt);
    cudaGetSymbolAddress((void**)&p_z, g_z);
    cudaGetSymbolAddress((void**)&p_mid, g_resid_mid);
    cudaGetSymbolAddress((void**)&p_y, g_y);
    cudaGetSymbolAddress((void**)&p_post, g_post);

    cudaFuncSetAttribute(tc_gemm_k<EPI_BIAS>,
                         cudaFuncAttributeMaxDynamicSharedMemorySize, SMEM_128_128);
    cudaFuncSetAttribute(tc_gemm_k<EPI_BIAS_RES>,
                         cudaFuncAttributeMaxDynamicSharedMemorySize, SMEM_128_128);
    cudaFuncSetAttribute(tc_gemm_k<EPI_BIAS_GELU>,
                         cudaFuncAttributeMaxDynamicSharedMemorySize, SMEM_128_128);
    cudaFuncSetAttribute(flash_k,
                         cudaFuncAttributeMaxDynamicSharedMemorySize, FLASH_SMEM);

    /* weight prep */
    pack_qkv_k<<<(N3 * D_RES + 255) / 256, 256>>>(WQ, WK, WV, bQ, bK, bV);
    transpose_k<<<dim3(32, 32), dim3(32, 8)>>>(WO, p_WOt, D_RES, D_RES);
    transpose_k<<<dim3(128, 32), dim3(32, 8)>>>(Win, p_Wint, D_RES, DMLP);
    transpose_k<<<dim3(32, 128), dim3(32, 8)>>>(Wout, p_Woutt, DMLP, D_RES);

    /* LN1 */
    layernorm_k<<<NTOK, 256>>>(resid_pre, ln1_w, ln1_b, p_xln);

    /* QKV = xln @ Wqkv + bias */
    tc_gemm_k<EPI_BIAS><<<dim3(N3 / 128, NTOK / 128), 256, SMEM_128_128>>>(
        p_xln, D_RES, p_Wqkvt, D_RES, p_qkv, N3, D_RES, p_bias, nullptr, 0);

    /* V^T per head */
    vtrans_k<<<dim3(SEQ / 32, DH / 32, BATCH * NH), dim3(32, 8)>>>(p_qkv, p_vt);

    /* fused attention: scores + softmax + PV */
    flash_k<<<dim3(8, BATCH * NH), 256, FLASH_SMEM>>>(p_qkv, p_vt, p_z);

    /* resid_mid = Z @ W_O + b_O + resid_pre */
    tc_gemm_k<EPI_BIAS_RES><<<dim3(D_RES / 128, NTOK / 128), 256, SMEM_128_128>>>(
        p_z, D_RES, p_WOt, D_RES, p_mid, D_RES, D_RES, bO, resid_pre, D_RES);

    /* LN2 */
    layernorm_k<<<NTOK, 256>>>(p_mid, ln2_w, ln2_b, p_y);

    /* post = gelu(y @ W_in + b_in) */
    tc_gemm_k<EPI_BIAS_GELU><<<dim3(DMLP / 128, NTOK / 128), 256, SMEM_128_128>>>(
        p_y, D_RES, p_Wint, D_RES, p_post, DMLP, D_RES, bin, nullptr, 0);

    /* out = post @ W_out + b_out + resid_mid */
    tc_gemm_k<EPI_BIAS_RES><<<dim3(D_RES / 128, NTOK / 128), 256, SMEM_128_128>>>(
        p_post, DMLP, p_Woutt, DMLP, out, D_RES, DMLP, bout, p_mid, D_RES);
}

// round 9
// speedup vs baseline: 6.0442x; 1.7208x over previous
#include <cuda_runtime.h>
#include <cuda_fp16.h>
#include <math.h>
#include <stdint.h>

#define D_RES  1024
#define NH     16
#define DH     64
#define DMLP   4096
#define SEQ    2048
#define BATCH  2
#define NTOK   (BATCH*SEQ)      /* 4096 */
#define N3     (3*D_RES)        /* 3072 */
#define EPSLN  1e-5f

/* ------------------------------------------------------------------ */
/* Scratch: __device__ globals                                         */
/* ------------------------------------------------------------------ */
__device__ __half g_Wqkv_t[N3 * D_RES];              /* [3072][1024] */
__device__ float  g_bias_qkv[N3];
__device__ __half g_WOt[D_RES * D_RES];
__device__ __half g_Wint[DMLP * D_RES];
__device__ __half g_Woutt[D_RES * DMLP];
__device__ __half g_xln[(size_t)NTOK * D_RES];
__device__ __half g_qkv[(size_t)NTOK * N3];
__device__ __half g_vt[(size_t)BATCH * NH * DH * SEQ];  /* [bh][e][k] */
__device__ __half g_z[(size_t)NTOK * D_RES];
__device__ float  g_resid_mid[(size_t)NTOK * D_RES];
__device__ __half g_y[(size_t)NTOK * D_RES];
__device__ __half g_post[(size_t)NTOK * DMLP];

/* ------------------------------------------------------------------ */
/* PTX helpers                                                         */
/* ------------------------------------------------------------------ */
__device__ __forceinline__ uint32_t smem_u32(const void* p) {
    uint32_t a;
    asm("{ .reg .u64 t; cvta.to.shared.u64 t, %1; cvt.u32.u64 %0, t; }" : "=r"(a) : "l"(p));
    return a;
}
__device__ __forceinline__ void cp16(uint32_t dst, const void* src) {
    asm volatile("cp.async.ca.shared.global [%0], [%1], 16;" :: "r"(dst), "l"(src));
}
#define CP_COMMIT()  asm volatile("cp.async.commit_group;" ::: "memory")
#define CP_WAIT0()   asm volatile("cp.async.wait_group 0;" ::: "memory")
#define CP_WAIT1()   asm volatile("cp.async.wait_group 1;" ::: "memory")

__device__ __forceinline__ void ldsm4(uint32_t a, uint32_t& r0, uint32_t& r1,
                                      uint32_t& r2, uint32_t& r3) {
    asm volatile("ldmatrix.sync.aligned.m8n8.x4.shared.b16 {%0,%1,%2,%3}, [%4];"
                 : "=r"(r0), "=r"(r1), "=r"(r2), "=r"(r3) : "r"(a));
}
__device__ __forceinline__ void mma_f16(float* c, const uint32_t* a,
                                        uint32_t b0, uint32_t b1) {
    asm volatile("mma.sync.aligned.m16n8k16.row.col.f32.f16.f16.f32 "
                 "{%0,%1,%2,%3}, {%4,%5,%6,%7}, {%8,%9}, {%0,%1,%2,%3};"
                 : "+f"(c[0]), "+f"(c[1]), "+f"(c[2]), "+f"(c[3])
                 : "r"(a[0]), "r"(a[1]), "r"(a[2]), "r"(a[3]), "r"(b0), "r"(b1));
}

/* ------------------------------------------------------------------ */
/* fp16 warp-MMA core. K-chunk 64 halves (128 B/row).                  */
/* SMEM row stride 72 halves (144 B) -> ldmatrix conflict-free.        */
/* ------------------------------------------------------------------ */
#define STRH 72
#define TILE_B (128 * STRH * 2)     /* 18432 B per 128-row tile */

template <int ROWS, int NT>
__device__ __forceinline__ void stage_tile_h(uint32_t s, const __half* __restrict__ g,
                                             int ld, int k0) {
    #pragma unroll
    for (int i = 0; i < (ROWS * 8) / NT; i++) {
        int u = threadIdx.x + i * NT;
        int r = u >> 3, c = u & 7;
        cp16(s + (uint32_t)((r * STRH + c * 8) * 2), g + (size_t)r * ld + k0 + c * 8);
    }
}

/* Warp grid: wm = wid/WN, wn = wid%WN. Warp tile (MT*16) x (NT*8).    */
template <int MT, int NT, int WN>
__device__ __forceinline__ void compute_chunk_h(uint32_t a_s, uint32_t b_s,
                                                float (&acc)[MT][NT][4]) {
    int lane = threadIdx.x & 31, wid = threadIdx.x >> 5;
    int wm = wid / WN, wn = wid % WN;
    uint32_t ab = a_s + (uint32_t)(((wm * (MT * 16) + (lane & 15)) * STRH
                                    + ((lane >> 4) << 3)) * 2);
    uint32_t bb = b_s + (uint32_t)(((wn * (NT * 8) + (lane & 15)) * STRH
                                    + ((lane >> 4) << 3)) * 2);
    #pragma unroll
    for (int ks = 0; ks < 4; ks++) {        /* 4 x k16 = 64 */
        uint32_t af[MT][4], bf[NT][2];
        #pragma unroll
        for (int mt = 0; mt < MT; mt++)
            ldsm4(ab + mt * (16 * STRH * 2) + ks * 32,
                  af[mt][0], af[mt][1], af[mt][2], af[mt][3]);
        #pragma unroll
        for (int p = 0; p < NT / 2; p++) {
            uint32_t r0, r1, r2, r3;
            ldsm4(bb + p * (16 * STRH * 2) + ks * 32, r0, r1, r2, r3);
            bf[2 * p][0] = r0; bf[2 * p][1] = r2;
            bf[2 * p + 1][0] = r1; bf[2 * p + 1][1] = r3;
        }
        #pragma unroll
        for (int mt = 0; mt < MT; mt++)
            #pragma unroll
            for (int nt = 0; nt < NT; nt++)
                mma_f16(acc[mt][nt], af[mt], bf[nt][0], bf[nt][1]);
    }
}

/* Dense pipelined K loop (BM=BN=128, 8 warps) */
__device__ __forceinline__ void mma_run_dense_h(uint32_t sb,
        const __half* __restrict__ A, int lda,
        const __half* __restrict__ Bt, int ldb, int nc, float (&acc)[4][4][4]) {
    uint32_t aS[2] = { sb, sb + 2u * TILE_B };
    uint32_t bS[2] = { sb + TILE_B, sb + 3u * TILE_B };

    stage_tile_h<128, 256>(aS[0], A, lda, 0);
    stage_tile_h<128, 256>(bS[0], Bt, ldb, 0);
    CP_COMMIT();

    for (int c = 0; c < nc; c++) {
        if (c + 1 < nc) {
            int nb = (c + 1) & 1;
            stage_tile_h<128, 256>(aS[nb], A, lda, (c + 1) * 64);
            stage_tile_h<128, 256>(bS[nb], Bt, ldb, (c + 1) * 64);
            CP_COMMIT();
            CP_WAIT1();
        } else {
            CP_WAIT0();
        }
        __syncthreads();
        compute_chunk_h<4, 4, 4>(aS[c & 1], bS[c & 1], acc);
        __syncthreads();
    }
}

__device__ __forceinline__ float gelu_exact(float x) {
    return 0.5f * x * (1.f + erff(x * 0.70710678118654752f));
}

enum { EPI_BIAS = 1, EPI_BIAS_RES = 2, EPI_BIAS_GELU = 3 };

/* HOUT: write __half (operand path); else fp32 (residual path) */
template <int EPI, bool HOUT>
__device__ __forceinline__ void epilogue_dense_h(float (&acc)[4][4][4],
        void* __restrict__ Cv, int ldc, int bm, int bn,
        const float* __restrict__ bias, const float* __restrict__ res, int ldres) {
    int lane = threadIdx.x & 31, wid = threadIdx.x >> 5;
    int wm = wid >> 2, wn = wid & 3;
    int r0 = bm + wm * 64 + (lane >> 2);
    int c0 = bn + wn * 32 + 2 * (lane & 3);
    #pragma unroll
    for (int mt = 0; mt < 4; mt++) {
        #pragma unroll
        for (int nt = 0; nt < 4; nt++) {
            int col = c0 + nt * 8;
            float2 bb = *(const float2*)(bias + col);
            #pragma unroll
            for (int h = 0; h < 2; h++) {
                int row = r0 + mt * 16 + h * 8;
                float v0 = acc[mt][nt][2 * h] + bb.x;
                float v1 = acc[mt][nt][2 * h + 1] + bb.y;
                if (EPI == EPI_BIAS_RES) {
                    float2 rr = *(const float2*)(res + (size_t)row * ldres + col);
                    v0 += rr.x; v1 += rr.y;
                }
                if (EPI == EPI_BIAS_GELU) { v0 = gelu_exact(v0); v1 = gelu_exact(v1); }
                if (HOUT) {
                    *(__half2*)((__half*)Cv + (size_t)row * ldc + col) =
                        __floats2half2_rn(v0, v1);
                } else {
                    *(float2*)((float*)Cv + (size_t)row * ldc + col) =
                        make_float2(v0, v1);
                }
            }
        }
    }
}

/* ------------------------------------------------------------------ */
/* Dense GEMM kernel                                                   */
/* ------------------------------------------------------------------ */
#define SMEM_DENSE (4 * TILE_B)    /* 73728 */

template <int EPI, bool HOUT>
__global__ void __launch_bounds__(256) h_gemm_k(const __half* __restrict__ A, int lda,
        const __half* __restrict__ Bt, int ldb, void* __restrict__ C, int ldc, int K,
        const float* __restrict__ bias, const float* __restrict__ res, int ldres) {
    extern __shared__ __half smh[];
    uint32_t sb = smem_u32(smh);
    int bm = blockIdx.y * 128, bn = blockIdx.x * 128;
    float acc[4][4][4] = {};
    mma_run_dense_h(sb, A + (size_t)bm * lda, lda, Bt + (size_t)bn * ldb, ldb,
                    K / 64, acc);
    epilogue_dense_h<EPI, HOUT>(acc, C, ldc, bm, bn, bias, res, ldres);
}

/* ------------------------------------------------------------------ */
/* Flash attention (fp16 operands, fp32 softmax/accum)                 */
/* SMEM halves: Q[128][72] K[128][72] V[2][64][72] P[2][128][72]       */
/*              + rowred 128x4 floats                                  */
/* ------------------------------------------------------------------ */
#define FQ   0
#define FK   (128 * STRH)
#define FV   (2 * 128 * STRH)
#define FP   (FV + 2 * 64 * STRH)
#define FREDB ((FP + 2 * 128 * STRH) * 2)          /* byte offset */
#define FLASH_SMEM (FREDB + 128 * 4 * 4)

__global__ void __launch_bounds__(256) flash_k(const __half* __restrict__ qkv,
                                               const __half* __restrict__ vt,
                                               __half* __restrict__ Z) {
    extern __shared__ __half smh[];
    uint32_t sb = smem_u32(smh);
    const uint32_t sQ = sb + FQ * 2;
    const uint32_t sK = sb + FK * 2;
    const uint32_t sV = sb + FV * 2;
    const uint32_t sP = sb + FP * 2;
    float* rowred = (float*)((char*)smh + FREDB);

    int bh = blockIdx.y, b = bh >> 4, h = bh & 15;
    int lane = threadIdx.x & 31, wid = threadIdx.x >> 5;
    int wm = wid >> 2, wn = wid & 3;

    const __half* qbase = qkv + (size_t)b * SEQ * N3 + h * DH;
    const __half* kbase = qbase + D_RES;
    const __half* vtb = vt + (size_t)bh * DH * SEQ;
    __half* Zb = Z + (size_t)b * SEQ * D_RES + h * DH;

    #pragma unroll 1
    for (int hf = 0; hf < 2; hf++) {
        int qt = hf ? (15 - (int)blockIdx.x) : (int)blockIdx.x;

        stage_tile_h<128, 256>(sQ, qbase + (size_t)qt * 128 * N3, N3, 0);
        CP_COMMIT();

        float m_i[8], l_i[8];
        float oacc[4][2][4] = {};
        #pragma unroll
        for (int s = 0; s < 8; s++) { m_i[s] = -1e30f; l_i[s] = 0.f; }

        for (int kt = 0; kt <= qt; kt++) {
            stage_tile_h<128, 256>(sK, kbase + (size_t)kt * 128 * N3, N3, 0);
            #pragma unroll
            for (int c = 0; c < 2; c++)
                stage_tile_h<64, 256>(sV + c * (64 * STRH * 2), vtb, SEQ,
                                      kt * 128 + c * 64);
            CP_COMMIT();
            CP_WAIT0();
            __syncthreads();

            /* S = Q K^T (single K-chunk: DH=64) */
            float sacc[4][4][4] = {};
            compute_chunk_h<4, 4, 4>(sQ, sK, sacc);

            int rl0 = wm * 64 + (lane >> 2);
            int cl0 = wn * 32 + 2 * (lane & 3);
            bool diag = (kt == qt);
            #pragma unroll
            for (int mt = 0; mt < 4; mt++)
                #pragma unroll
                for (int nt = 0; nt < 4; nt++)
                    #pragma unroll
                    for (int hh = 0; hh < 2; hh++) {
                        int r = rl0 + mt * 16 + 8 * hh;
                        int c = cl0 + nt * 8;
                        float v0 = sacc[mt][nt][2 * hh] * 0.125f;
                        float v1 = sacc[mt][nt][2 * hh + 1] * 0.125f;
                        if (diag) {
                            if (c > r)     v0 = -1e30f;
                            if (c + 1 > r) v1 = -1e30f;
                        }
                        sacc[mt][nt][2 * hh] = v0;
                        sacc[mt][nt][2 * hh + 1] = v1;
                    }

            /* row-max */
            #pragma unroll
            for (int mt = 0; mt < 4; mt++)
                #pragma unroll
                for (int hh = 0; hh < 2; hh++) {
                    float v = -1e30f;
                    #pragma unroll
                    for (int nt = 0; nt < 4; nt++) {
                        v = fmaxf(v, sacc[mt][nt][2 * hh]);
                        v = fmaxf(v, sacc[mt][nt][2 * hh + 1]);
                    }
                    v = fmaxf(v, __shfl_xor_sync(0xffffffffu, v, 1));
                    v = fmaxf(v, __shfl_xor_sync(0xffffffffu, v, 2));
                    if ((lane & 3) == 0)
                        rowred[(rl0 + mt * 16 + 8 * hh) * 4 + wn] = v;
                }
            __syncthreads();
            float m_new[8], alpha[8];
            #pragma unroll
            for (int mt = 0; mt < 4; mt++)
                #pragma unroll
                for (int hh = 0; hh < 2; hh++) {
                    int s = mt * 2 + hh;
                    const float* rr = rowred + (rl0 + mt * 16 + 8 * hh) * 4;
                    float tm = fmaxf(fmaxf(rr[0], rr[1]), fmaxf(rr[2], rr[3]));
                    m_new[s] = fmaxf(m_i[s], tm);
                    alpha[s] = __expf(m_i[s] - m_new[s]);
                    m_i[s] = m_new[s];
                }
            __syncthreads();

            /* P = exp(S - m) -> half smem; partial row sums */
            #pragma unroll
            for (int mt = 0; mt < 4; mt++)
                #pragma unroll
                for (int hh = 0; hh < 2; hh++) {
                    int s = mt * 2 + hh;
                    float ps = 0.f;
                    int prow = (wn >> 1) * (128 * STRH)
                             + (rl0 + mt * 16 + 8 * hh) * STRH
                             + (wn & 1) * 32 + 2 * (lane & 3);
                    #pragma unroll
                    for (int nt = 0; nt < 4; nt++) {
                        float p0 = __expf(sacc[mt][nt][2 * hh] - m_new[s]);
                        float p1 = __expf(sacc[mt][nt][2 * hh + 1] - m_new[s]);
                        ps += p0 + p1;
                        *(__half2*)(smh + FP + prow + nt * 8) = __floats2half2_rn(p0, p1);
                    }
                    ps += __shfl_xor_sync(0xffffffffu, ps, 1);
                    ps += __shfl_xor_sync(0xffffffffu, ps, 2);
                    if ((lane & 3) == 0)
                        rowred[(rl0 + mt * 16 + 8 * hh) * 4 + wn] = ps;
                }
            __syncthreads();
            #pragma unroll
            for (int mt = 0; mt < 4; mt++)
                #pragma unroll
                for (int hh = 0; hh < 2; hh++) {
                    int s = mt * 2 + hh;
                    const float* rr = rowred + (rl0 + mt * 16 + 8 * hh) * 4;
                    l_i[s] = l_i[s] * alpha[s] + (rr[0] + rr[1] + rr[2] + rr[3]);
                    #pragma unroll
                    for (int nt = 0; nt < 2; nt++) {
                        oacc[mt][nt][2 * hh]     *= alpha[s];
                        oacc[mt][nt][2 * hh + 1] *= alpha[s];
                    }
                }

            /* O += P V (2 chunks of 64) */
            #pragma unroll
            for (int c = 0; c < 2; c++)
                compute_chunk_h<4, 2, 4>(sP + c * (128 * STRH * 2),
                                         sV + c * (64 * STRH * 2), oacc);
            __syncthreads();
        }

        /* Z = O / l  (half) */
        #pragma unroll
        for (int mt = 0; mt < 4; mt++)
            #pragma unroll
            for (int hh = 0; hh < 2; hh++) {
                int s = mt * 2 + hh;
                float inv = 1.f / l_i[s];
                int row = qt * 128 + wm * 64 + mt * 16 + (lane >> 2) + 8 * hh;
                #pragma unroll
                for (int nt = 0; nt < 2; nt++) {
                    int col = wn * 16 + nt * 8 + 2 * (lane & 3);
                    *(__half2*)(Zb + (size_t)row * D_RES + col) =
                        __floats2half2_rn(oacc[mt][nt][2 * hh] * inv,
                                          oacc[mt][nt][2 * hh + 1] * inv);
                }
            }
        __syncthreads();
    }
}

/* ------------------------------------------------------------------ */
/* LayerNorm: fp32 in -> half out (single pass)                        */
/* ------------------------------------------------------------------ */
__global__ void __launch_bounds__(256) layernorm_h_k(const float* __restrict__ in,
        const float* __restrict__ w, const float* __restrict__ b,
        __half* __restrict__ out) {
    int row = blockIdx.x, t = threadIdx.x;
    const float* x = in + (size_t)row * D_RES;
    float4 v = *(const float4*)(x + t * 4);
    float s = v.x + v.y + v.z + v.w;
    float q = v.x * v.x + v.y * v.y + v.z * v.z + v.w * v.w;
    #pragma unroll
    for (int o = 16; o > 0; o >>= 1) {
        s += __shfl_xor_sync(0xffffffffu, s, o);
        q += __shfl_xor_sync(0xffffffffu, q, o);
    }
    __shared__ float rs[8], rq[8];
    int wid = t >> 5;
    if ((t & 31) == 0) { rs[wid] = s; rq[wid] = q; }
    __syncthreads();
    s = rs[0] + rs[1] + rs[2] + rs[3] + rs[4] + rs[5] + rs[6] + rs[7];
    q = rq[0] + rq[1] + rq[2] + rq[3] + rq[4] + rq[5] + rq[6] + rq[7];
    float mean = s * (1.f / D_RES);
    float inv = rsqrtf(q * (1.f / D_RES) - mean * mean + EPSLN);
    float4 wv = *(const float4*)(w + t * 4);
    float4 bv = *(const float4*)(b + t * 4);
    __half* orow = out + (size_t)row * D_RES + t * 4;
    *(__half2*)(orow)     = __floats2half2_rn((v.x - mean) * inv * wv.x + bv.x,
                                              (v.y - mean) * inv * wv.y + bv.y);
    *(__half2*)(orow + 2) = __floats2half2_rn((v.z - mean) * inv * wv.z + bv.z,
                                              (v.w - mean) * inv * wv.w + bv.w);
}

/* ------------------------------------------------------------------ */
/* Weight packing / transposes (fp32 -> half)                          */
/* ------------------------------------------------------------------ */
__global__ void pack_qkv_k(const float* __restrict__ WQ, const float* __restrict__ WK,
                           const float* __restrict__ WV, const float* __restrict__ bQ,
                           const float* __restrict__ bK, const float* __restrict__ bV) {
    int idx = blockIdx.x * blockDim.x + threadIdx.x;
    if (idx < N3 * D_RES) {
        int n = idx / D_RES;
        int d = idx % D_RES;
        int sel = n / D_RES;
        int c = n % D_RES;
        int h = c / DH, e = c % DH;
        const float* W = (sel == 0) ? WQ : (sel == 1) ? WK : WV;
        g_Wqkv_t[idx] = __float2half_rn(W[((size_t)h * D_RES + d) * DH + e]);
    }
    if (idx < N3) {
        const float* bb = (idx < D_RES) ? bQ : (idx < 2 * D_RES) ? bK : bV;
        g_bias_qkv[idx] = bb[idx % D_RES];
    }
}

__global__ void transpose_h_k(const float* __restrict__ in, __half* __restrict__ out,
                              int R, int C) {
    __shared__ float tile[32][33];
    int c0 = blockIdx.x * 32, r0 = blockIdx.y * 32;
    for (int i = threadIdx.y; i < 32; i += 8)
        tile[i][threadIdx.x] = in[(size_t)(r0 + i) * C + c0 + threadIdx.x];
    __syncthreads();
    for (int i = threadIdx.y; i < 32; i += 8)
        out[(size_t)(c0 + i) * R + r0 + threadIdx.x] =
            __float2half_rn(tile[threadIdx.x][i]);
}

/* vt[bh][e][k] = qkv[b][k][2048 + h*64 + e]  (half -> half) */
__global__ void vtrans_h_k(const __half* __restrict__ qkv, __half* __restrict__ vt) {
    __shared__ __half tile[32][36];
    int bh = blockIdx.z, b = bh >> 4, h = bh & 15;
    const __half* src = qkv + (size_t)b * SEQ * N3 + 2 * D_RES + h * DH;
    int k0 = blockIdx.x * 32, e0 = blockIdx.y * 32;
    for (int i = threadIdx.y; i < 32; i += 8)
        tile[i][threadIdx.x] = src[(size_t)(k0 + i) * N3 + e0 + threadIdx.x];
    __syncthreads();
    __half* dst = vt + (size_t)bh * DH * SEQ;
    for (int i = threadIdx.y; i < 32; i += 8)
        dst[(size_t)(e0 + i) * SEQ + k0 + threadIdx.x] = tile[threadIdx.x][i];
}

/* ------------------------------------------------------------------ */
/* Launch                                                              */
/* ------------------------------------------------------------------ */
extern "C" void kernel_launch(void* const* d_in, const int* in_sizes, int n_in,
                              void* d_out, int out_size) {
    const float* resid_pre = (const float*)d_in[0];
    const float* ln1_w = (const float*)d_in[1];
    const float* ln1_b = (const float*)d_in[2];
    const float* WQ = (const float*)d_in[3];
    const float* bQ = (const float*)d_in[4];
    const float* WK = (const float*)d_in[5];
    const float* bK = (const float*)d_in[6];
    const float* WV = (const float*)d_in[7];
    const float* bV = (const float*)d_in[8];
    const float* WO = (const float*)d_in[9];
    const float* bO = (const float*)d_in[10];
    const float* ln2_w = (const float*)d_in[11];
    const float* ln2_b = (const float*)d_in[12];
    const float* Win  = (const float*)d_in[13];
    const float* bin  = (const float*)d_in[14];
    const float* Wout = (const float*)d_in[15];
    const float* bout = (const float*)d_in[16];
    float* out = (float*)d_out;

    __half *p_Wqkvt, *p_WOt, *p_Wint, *p_Woutt, *p_xln, *p_qkv, *p_vt, *p_z,
           *p_y, *p_post;
    float *p_bias, *p_mid;
    cudaGetSymbolAddress((void**)&p_Wqkvt, g_Wqkv_t);
    cudaGetSymbolAddress((void**)&p_bias, g_bias_qkv);
    cudaGetSymbolAddress((void**)&p_WOt, g_WOt);
    cudaGetSymbolAddress((void**)&p_Wint, g_Wint);
    cudaGetSymbolAddress((void**)&p_Woutt, g_Woutt);
    cudaGetSymbolAddress((void**)&p_xln, g_xln);
    cudaGetSymbolAddress((void**)&p_qkv, g_qkv);
    cudaGetSymbolAddress((void**)&p_vt, g_vt);
    cudaGetSymbolAddress((void**)&p_z, g_z);
    cudaGetSymbolAddress((void**)&p_mid, g_resid_mid);
    cudaGetSymbolAddress((void**)&p_y, g_y);
    cudaGetSymbolAddress((void**)&p_post, g_post);

    cudaFuncSetAttribute(h_gemm_k<EPI_BIAS, true>,
                         cudaFuncAttributeMaxDynamicSharedMemorySize, SMEM_DENSE);
    cudaFuncSetAttribute(h_gemm_k<EPI_BIAS_RES, false>,
                         cudaFuncAttributeMaxDynamicSharedMemorySize, SMEM_DENSE);
    cudaFuncSetAttribute(h_gemm_k<EPI_BIAS_GELU, true>,
                         cudaFuncAttributeMaxDynamicSharedMemorySize, SMEM_DENSE);
    cudaFuncSetAttribute(flash_k,
                         cudaFuncAttributeMaxDynamicSharedMemorySize, FLASH_SMEM);

    /* weight prep */
    pack_qkv_k<<<(N3 * D_RES + 255) / 256, 256>>>(WQ, WK, WV, bQ, bK, bV);
    transpose_h_k<<<dim3(32, 32), dim3(32, 8)>>>(WO, p_WOt, D_RES, D_RES);
    transpose_h_k<<<dim3(128, 32), dim3(32, 8)>>>(Win, p_Wint, D_RES, DMLP);
    transpose_h_k<<<dim3(32, 128), dim3(32, 8)>>>(Wout, p_Woutt, DMLP, D_RES);

    /* LN1 (fp32 -> half) */
    layernorm_h_k<<<NTOK, 256>>>(resid_pre, ln1_w, ln1_b, p_xln);

    /* QKV = xln @ Wqkv + bias -> half */
    h_gemm_k<EPI_BIAS, true><<<dim3(N3 / 128, NTOK / 128), 256, SMEM_DENSE>>>(
        p_xln, D_RES, p_Wqkvt, D_RES, p_qkv, N3, D_RES, p_bias, nullptr, 0);

    /* V^T per head */
    vtrans_h_k<<<dim3(SEQ / 32, DH / 32, BATCH * NH), dim3(32, 8)>>>(p_qkv, p_vt);

    /* fused attention */
    flash_k<<<dim3(8, BATCH * NH), 256, FLASH_SMEM>>>(p_qkv, p_vt, p_z);

    /* resid_mid = Z @ W_O + b_O + resid_pre -> fp32 */
    h_gemm_k<EPI_BIAS_RES, false><<<dim3(D_RES / 128, NTOK / 128), 256, SMEM_DENSE>>>(
        p_z, D_RES, p_WOt, D_RES, p_mid, D_RES, D_RES, bO, resid_pre, D_RES);

    /* LN2 (fp32 -> half) */
    layernorm_h_k<<<NTOK, 256>>>(p_mid, ln2_w, ln2_b, p_y);

    /* post = gelu(y @ W_in + b_in) -> half */
    h_gemm_k<EPI_BIAS_GELU, true><<<dim3(DMLP / 128, NTOK / 128), 256, SMEM_DENSE>>>(
        p_y, D_RES, p_Wint, D_RES, p_post, DMLP, D_RES, bin, nullptr, 0);

    /* out = post @ W_out + b_out + resid_mid -> fp32 */
    h_gemm_k<EPI_BIAS_RES, false><<<dim3(D_RES / 128, NTOK / 128), 256, SMEM_DENSE>>>(
        p_post, DMLP, p_Woutt, DMLP, out, D_RES, DMLP, bout, p_mid, D_RES);
}